// round 15
// baseline (speedup 1.0000x reference)
#include <cuda_runtime.h>
#include <math.h>

#define Bz 8
#define Tz 512
#define Ez 64
#define Hz 128
#define TC 32     // tokens per CTA
#define NC 16     // chunks per batch
#define NCTA (Bz*NC)
#define THR 256

#define P1 68
#define P2 132

// Per-CTA partial layout (floats): D-weighted grads only
#define OF2_W1D 0
#define OF2_B1D 8192
#define OF2_W2D 8320
#define OF2_B2D 16512
#define PARTSZ2 16576

// Output offsets
#define O_LOSS 0
#define O_MW1  512
#define O_MB1  66048
#define O_MW2  67072
#define O_MB2  132608
#define O_SW1  133120
#define O_SB1  198656
#define O_SW2  199680
#define O_SB2  265216

#define LNETA  (-0.0512932943875506f)
#define LNBETA (-6.9077552789821370f)
#define INV949 (1.0537407798735f)
#define CORRK  (0.0526870389936f)

__device__ __align__(16) float g_np[2*NCTA*Ez];
__device__ __align__(16) float g_lossp[Bz*Tz];
__device__ __align__(16) float g_part[NCTA*PARTSZ2];
__device__ __align__(16) float g_corr[Bz*PARTSZ2];
// Per-batch sense barriers (32-int stride = 128B padding) + global loss counter
__device__ unsigned g_bc[Bz*32];
__device__ volatile unsigned g_bp[Bz*32];
__device__ unsigned g_lcount;

__device__ __forceinline__ float fast_sig(float z) {
    return __fdividef(1.f, 1.f + __expf(-z));
}

// ---------------------------------------------------------------------------
// Single fused kernel: 128 CTAs x 256 threads, 255-reg budget (R13/R14 base)
// + per-batch barriers (16 CTAs each) + last-CTA loss finalize.
// ---------------------------------------------------------------------------
#define SM_FLOATS 36016
__global__ __launch_bounds__(THR, 1) void k_main(const float* __restrict__ x,
                                                 const float* __restrict__ WK,
                                                 const float* __restrict__ WV,
                                                 const float* __restrict__ W1,
                                                 const float* __restrict__ b1,
                                                 const float* __restrict__ W2,
                                                 const float* __restrict__ b2,
                                                 const float* __restrict__ SW1,
                                                 const float* __restrict__ Sb1,
                                                 const float* __restrict__ SW2,
                                                 const float* __restrict__ Sb2,
                                                 float* __restrict__ out) {
    extern __shared__ float sm[];
    float* sWK  = sm;                 // 64 x P1
    float* sWV  = sm + 4352;          // 64 x P1
    float* sW1  = sm;                 // 128 x P1 overlay (WK/WV dead)
    float* sx   = sm + 8704;          // 32x64 (phase0 only)
    float* sW2  = sm + 8704;          // 64 x P2 overlay
    float* sk   = sm + 17152;         // 32x64 (raw silu k)
    float* sv   = sk  + 2048;         // 32x64 (raw silu v)
    float* sh   = sv  + 2048;         // 32x128
    float* ss   = sh  + 4096;         // 32x128
    float* sdy  = ss  + 4096;         // 32x64
    float* sdz  = sdy + 2048;         // 32x128
    float* scD  = sdz + 4096;         // 32
    float* scC  = scD + 32;           // 32
    float* sinvk= scC + 32;           // 64
    float* sinvv= sinvk + 64;         // 64
    float* sloss= sinvv + 64;         // 32
    float* sb1  = sloss + 32;         // 128
    float* sb2  = sb1 + 128;          // 64
    float* sflag= sb2 + 64;           // 1   -> 36001 <= 36016

    const int bid = blockIdx.x;
    const int b   = bid >> 4;
    const int cid = bid & 15;
    const int t0  = cid * TC;
    const int tid = threadIdx.x;
    const int lane = tid & 31, wp = tid >> 5;   // 8 warps, 4 tokens each

    // ---- phase 0 loads ----
    #pragma unroll
    for (int i = tid*4; i < 4096; i += 1024) {
        int e = i >> 6, j = i & 63;
        *(float4*)&sWK[e*P1 + j] = *(const float4*)&WK[i];
        *(float4*)&sWV[e*P1 + j] = *(const float4*)&WV[i];
    }
    #pragma unroll
    for (int i = tid*4; i < 2048; i += 1024)
        *(float4*)&sx[i] = *(const float4*)&x[(b*Tz + t0)*64 + i];
    if (tid < 64)       sinvk[tid] = 0.f;
    else if (tid < 128) sinvv[tid - 64] = 0.f;
    if (tid >= 128 && tid < 160) {
        int tl = tid - 128;
        float n1 = (float)(Tz - (t0 + tl));
        scD[tl] = -0.05f * __expf(n1 * LNETA);
        scC[tl] = CORRK  * __expf(n1 * LNBETA);
    }
    __syncthreads();

    // ---- phase 0: silu projections (4 tokens/warp, 4x4 tiles) ----
    {
        float acc[4][4];
        #pragma unroll
        for (int r = 0; r < 4; r++)
            #pragma unroll
            for (int tt = 0; tt < 4; tt++) acc[r][tt] = 0.f;
        #pragma unroll
        for (int j = 0; j < 64; j += 4) {
            float xv[4][4];
            #pragma unroll
            for (int tt = 0; tt < 4; tt++) {
                float4 q = *(const float4*)&sx[(wp*4 + tt)*64 + j];
                xv[tt][0] = q.x; xv[tt][1] = q.y; xv[tt][2] = q.z; xv[tt][3] = q.w;
            }
            float4 w4[4];
            w4[0] = *(const float4*)&sWK[(lane     )*P1 + j];
            w4[1] = *(const float4*)&sWK[(lane + 32)*P1 + j];
            w4[2] = *(const float4*)&sWV[(lane     )*P1 + j];
            w4[3] = *(const float4*)&sWV[(lane + 32)*P1 + j];
            #pragma unroll
            for (int r = 0; r < 4; r++) {
                const float* w = (const float*)&w4[r];
                #pragma unroll
                for (int jj = 0; jj < 4; jj++)
                    #pragma unroll
                    for (int tt = 0; tt < 4; tt++)
                        acc[r][tt] += w[jj] * xv[tt][jj];
            }
        }
        #pragma unroll
        for (int r = 0; r < 4; r++) {
            int e = lane + 32*(r & 1);
            float sq = 0.f;
            #pragma unroll
            for (int tt = 0; tt < 4; tt++) {
                float z = acc[r][tt];
                float s = z * fast_sig(z);
                int t = wp*4 + tt;
                if (r < 2) sk[t*64 + e] = s;
                else       sv[t*64 + e] = s;
                sq += s * s;
            }
            if (r < 2) atomicAdd(&sinvk[e], sq);
            else       atomicAdd(&sinvv[e], sq);
        }
    }
    __syncthreads();

    if (tid < 64)       g_np[bid*64 + tid] = sinvk[tid];
    else if (tid < 128) g_np[(NCTA + bid)*64 + tid - 64] = sinvv[tid - 64];

    // ---- per-batch barrier #1 (W1/W2/b1/b2 loads overlap the spin) ----
    __threadfence();
    __syncthreads();
    if (tid == 0) {
        unsigned my = g_bp[b*32];
        unsigned old = atomicAdd(&g_bc[b*32], 1);
        if (old == NC - 1) {
            g_bc[b*32] = 0;
            __threadfence();
            atomicAdd((unsigned*)&g_bp[b*32], 1);
        } else {
            while (g_bp[b*32] == my) { }
        }
        __threadfence();
    }
    #pragma unroll
    for (int i = tid*4; i < 8192; i += 1024)
        *(float4*)&sW1[(i >> 6)*P1 + (i & 63)] = *(const float4*)&W1[b*8192 + i];
    #pragma unroll
    for (int i = tid*4; i < 8192; i += 1024)
        *(float4*)&sW2[(i >> 7)*P2 + (i & 127)] = *(const float4*)&W2[b*8192 + i];
    if (tid < 128)      sb1[tid] = b1[b*128 + tid];
    else if (tid < 192) sb2[tid - 128] = b2[b*64 + tid - 128];
    __syncthreads();

    // ---- reduce norms ----
    if (tid < 64) {
        float s = 0.f, s2 = 0.f;
        #pragma unroll
        for (int c = 0; c < NC; c++) {
            s  += g_np[(b*NC + c)*64 + tid];
            s2 += g_np[(NCTA + b*NC + c)*64 + tid];
        }
        sinvk[tid] = (s  > 0.f) ? rsqrtf(s)  : 0.f;
        sinvv[tid] = (s2 > 0.f) ? rsqrtf(s2) : 0.f;
    }
    __syncthreads();

    // ---- z = W1 (k*invk) + b1 ; h = silu(z) ----
    {
        float acc[4][4];
        #pragma unroll
        for (int r = 0; r < 4; r++) {
            float bv = sb1[lane + 32*r];
            #pragma unroll
            for (int tt = 0; tt < 4; tt++) acc[r][tt] = bv;
        }
        #pragma unroll
        for (int j = 0; j < 64; j += 4) {
            float4 iv = *(const float4*)&sinvk[j];
            float kv[4][4];
            #pragma unroll
            for (int tt = 0; tt < 4; tt++) {
                float4 q = *(const float4*)&sk[(wp*4 + tt)*64 + j];
                kv[tt][0] = q.x * iv.x; kv[tt][1] = q.y * iv.y;
                kv[tt][2] = q.z * iv.z; kv[tt][3] = q.w * iv.w;
            }
            float4 w4[4];
            #pragma unroll
            for (int r = 0; r < 4; r++)
                w4[r] = *(const float4*)&sW1[(lane + 32*r)*P1 + j];
            #pragma unroll
            for (int r = 0; r < 4; r++) {
                const float* w = (const float*)&w4[r];
                #pragma unroll
                for (int jj = 0; jj < 4; jj++)
                    #pragma unroll
                    for (int tt = 0; tt < 4; tt++)
                        acc[r][tt] += w[jj] * kv[tt][jj];
            }
        }
        #pragma unroll
        for (int r = 0; r < 4; r++)
            #pragma unroll
            for (int tt = 0; tt < 4; tt++) {
                int idx = (wp*4 + tt)*128 + lane + 32*r;
                float z  = acc[r][tt];
                float sg = fast_sig(z);
                ss[idx] = sg;
                sh[idx] = z * sg;
            }
    }
    __syncwarp();

    // ---- y = W2 h + b2 ; dy = (y - v*invv)/256 ; loss ----
    {
        float acc[2][4];
        #pragma unroll
        for (int r = 0; r < 2; r++) {
            float bv = sb2[lane + 32*r];
            #pragma unroll
            for (int tt = 0; tt < 4; tt++) acc[r][tt] = bv;
        }
        #pragma unroll
        for (int j = 0; j < 128; j += 4) {
            float hv[4][4];
            #pragma unroll
            for (int tt = 0; tt < 4; tt++) {
                float4 q = *(const float4*)&sh[(wp*4 + tt)*128 + j];
                hv[tt][0] = q.x; hv[tt][1] = q.y; hv[tt][2] = q.z; hv[tt][3] = q.w;
            }
            float4 w40 = *(const float4*)&sW2[(lane     )*P2 + j];
            float4 w41 = *(const float4*)&sW2[(lane + 32)*P2 + j];
            const float* w0 = (const float*)&w40;
            const float* w1 = (const float*)&w41;
            #pragma unroll
            for (int jj = 0; jj < 4; jj++)
                #pragma unroll
                for (int tt = 0; tt < 4; tt++) {
                    acc[0][tt] += w0[jj] * hv[tt][jj];
                    acc[1][tt] += w1[jj] * hv[tt][jj];
                }
        }
        float iv0 = sinvv[lane], iv1 = sinvv[lane + 32];
        #pragma unroll
        for (int tt = 0; tt < 4; tt++) {
            int t = wp*4 + tt;
            float d0 = acc[0][tt] - sv[t*64 + lane]      * iv0;
            float d1 = acc[1][tt] - sv[t*64 + lane + 32] * iv1;
            sdy[t*64 + lane]      = d0 * (1.f/256.f);
            sdy[t*64 + lane + 32] = d1 * (1.f/256.f);
            float l = d0*d0 + d1*d1;
            #pragma unroll
            for (int o = 16; o; o >>= 1) l += __shfl_xor_sync(0xffffffffu, l, o);
            if (lane == 0) sloss[t] = l;
        }
    }
    __syncwarp();

    // ---- dh = W2^T dy ; dz ----
    {
        float acc[4][4];
        #pragma unroll
        for (int r = 0; r < 4; r++)
            #pragma unroll
            for (int tt = 0; tt < 4; tt++) acc[r][tt] = 0.f;
        #pragma unroll
        for (int e = 0; e < 64; e += 4) {
            float dv[4][4];
            #pragma unroll
            for (int tt = 0; tt < 4; tt++) {
                float4 q = *(const float4*)&sdy[(wp*4 + tt)*64 + e];
                dv[tt][0] = q.x; dv[tt][1] = q.y; dv[tt][2] = q.z; dv[tt][3] = q.w;
            }
            #pragma unroll
            for (int ee = 0; ee < 4; ee++) {
                float wv[4];
                #pragma unroll
                for (int r = 0; r < 4; r++) wv[r] = sW2[(e + ee)*P2 + lane + 32*r];
                #pragma unroll
                for (int r = 0; r < 4; r++)
                    #pragma unroll
                    for (int tt = 0; tt < 4; tt++)
                        acc[r][tt] += wv[r] * dv[tt][ee];
            }
        }
        #pragma unroll
        for (int r = 0; r < 4; r++)
            #pragma unroll
            for (int tt = 0; tt < 4; tt++) {
                int idx = (wp*4 + tt)*128 + lane + 32*r;
                float sg = ss[idx], hv = sh[idx];
                sdz[idx] = acc[r][tt] * (sg + hv * (1.f - sg));
            }
    }
    __syncthreads();

    // ---- D-weighted outer products: 8h x 4e tile (invk folded into ks) ----
    const int e0 = (tid & 15) * 4;
    const int h0 = (tid >> 4) * 8;
    const float4 ivk = *(const float4*)&sinvk[e0];
    float a1[8][4], a2[4][8];
    #pragma unroll
    for (int i = 0; i < 8; i++)
        #pragma unroll
        for (int j = 0; j < 4; j++) { a1[i][j] = 0.f; a2[j][i] = 0.f; }

    #pragma unroll 4
    for (int t = 0; t < TC; t++) {
        float cd = scD[t];
        float4 kq = *(const float4*)&sk[t*64 + e0];
        float ks[4] = {cd*kq.x*ivk.x, cd*kq.y*ivk.y, cd*kq.z*ivk.z, cd*kq.w*ivk.w};
        float4 z0 = *(const float4*)&sdz[t*128 + h0];
        float4 z1 = *(const float4*)&sdz[t*128 + h0 + 4];
        float dzv[8] = {z0.x, z0.y, z0.z, z0.w, z1.x, z1.y, z1.z, z1.w};
        #pragma unroll
        for (int i = 0; i < 8; i++)
            #pragma unroll
            for (int j = 0; j < 4; j++) a1[i][j] += dzv[i] * ks[j];
        float4 dq = *(const float4*)&sdy[t*64 + e0];
        float dys[4] = {cd*dq.x, cd*dq.y, cd*dq.z, cd*dq.w};
        float4 h0q = *(const float4*)&sh[t*128 + h0];
        float4 h1q = *(const float4*)&sh[t*128 + h0 + 4];
        float hv[8] = {h0q.x, h0q.y, h0q.z, h0q.w, h1q.x, h1q.y, h1q.z, h1q.w};
        #pragma unroll
        for (int j = 0; j < 4; j++)
            #pragma unroll
            for (int i = 0; i < 8; i++) a2[j][i] += dys[j] * hv[i];
    }

    float* p = g_part + (size_t)bid * PARTSZ2;
    #pragma unroll
    for (int i = 0; i < 8; i++)
        *(float4*)&p[OF2_W1D + (h0 + i)*64 + e0] =
            make_float4(a1[i][0], a1[i][1], a1[i][2], a1[i][3]);
    #pragma unroll
    for (int j = 0; j < 4; j++) {
        *(float4*)&p[OF2_W2D + (e0 + j)*128 + h0] =
            make_float4(a2[j][0], a2[j][1], a2[j][2], a2[j][3]);
        *(float4*)&p[OF2_W2D + (e0 + j)*128 + h0 + 4] =
            make_float4(a2[j][4], a2[j][5], a2[j][6], a2[j][7]);
    }
    if (tid < 128) {
        float aD = 0.f;
        #pragma unroll 4
        for (int t = 0; t < TC; t++) aD += scD[t] * sdz[t*128 + tid];
        p[OF2_B1D + tid] = aD;
    } else if (tid < 192) {
        int e = tid - 128;
        float aD = 0.f;
        #pragma unroll 4
        for (int t = 0; t < TC; t++) aD += scD[t] * sdy[t*64 + e];
        p[OF2_B2D + e] = aD;
    }
    if (tid < TC) g_lossp[b*Tz + t0 + tid] = sloss[tid];

    // ---- correction (last chunk per batch; invk folded) ----
    if (cid == 15) {
        #pragma unroll
        for (int i = 0; i < 8; i++)
            #pragma unroll
            for (int j = 0; j < 4; j++) { a1[i][j] = 0.f; a2[j][i] = 0.f; }
        for (int t = 16; t < TC; t++) {
            float cc = scC[t];
            float4 kq = *(const float4*)&sk[t*64 + e0];
            float ks[4] = {cc*kq.x*ivk.x, cc*kq.y*ivk.y, cc*kq.z*ivk.z, cc*kq.w*ivk.w};
            float4 z0 = *(const float4*)&sdz[t*128 + h0];
            float4 z1 = *(const float4*)&sdz[t*128 + h0 + 4];
            float dzv[8] = {z0.x, z0.y, z0.z, z0.w, z1.x, z1.y, z1.z, z1.w};
            #pragma unroll
            for (int i = 0; i < 8; i++)
                #pragma unroll
                for (int j = 0; j < 4; j++) a1[i][j] += dzv[i] * ks[j];
            float4 dq = *(const float4*)&sdy[t*64 + e0];
            float dys[4] = {cc*dq.x, cc*dq.y, cc*dq.z, cc*dq.w};
            float4 h0q = *(const float4*)&sh[t*128 + h0];
            float4 h1q = *(const float4*)&sh[t*128 + h0 + 4];
            float hv[8] = {h0q.x, h0q.y, h0q.z, h0q.w, h1q.x, h1q.y, h1q.z, h1q.w};
            #pragma unroll
            for (int j = 0; j < 4; j++)
                #pragma unroll
                for (int i = 0; i < 8; i++) a2[j][i] += dys[j] * hv[i];
        }
        float* q = g_corr + (size_t)b * PARTSZ2;
        #pragma unroll
        for (int i = 0; i < 8; i++)
            *(float4*)&q[OF2_W1D + (h0 + i)*64 + e0] =
                make_float4(a1[i][0], a1[i][1], a1[i][2], a1[i][3]);
        #pragma unroll
        for (int j = 0; j < 4; j++) {
            *(float4*)&q[OF2_W2D + (e0 + j)*128 + h0] =
                make_float4(a2[j][0], a2[j][1], a2[j][2], a2[j][3]);
            *(float4*)&q[OF2_W2D + (e0 + j)*128 + h0 + 4] =
                make_float4(a2[j][4], a2[j][5], a2[j][6], a2[j][7]);
        }
        if (tid < 128) {
            float aC = 0.f;
            for (int t = 16; t < TC; t++) aC += scC[t] * sdz[t*128 + tid];
            q[OF2_B1D + tid] = aC;
        } else if (tid < 192) {
            int e = tid - 128;
            float aC = 0.f;
            for (int t = 16; t < TC; t++) aC += scC[t] * sdy[t*64 + e];
            q[OF2_B2D + e] = aC;
        }
    }

    // ---- per-batch barrier #2, then per-batch output reduction ----
    __threadfence();
    __syncthreads();
    if (tid == 0) {
        unsigned my = g_bp[b*32];
        unsigned old = atomicAdd(&g_bc[b*32], 1);
        if (old == NC - 1) {
            g_bc[b*32] = 0;
            __threadfence();
            atomicAdd((unsigned*)&g_bp[b*32], 1);
        } else {
            while (g_bp[b*32] == my) { }
        }
        __threadfence();
    }
    __syncthreads();

    // batch b's 16 CTAs reduce batch b's 4144 vec4 items
    for (int j = cid * THR + tid; j < 4144; j += NC * THR) {
        int ofD, r, gidx, segM, segS;
        const float* S0p;
        if (j < 2048)      { ofD = OF2_W1D; r = j*4;        gidx = b*8192 + r;
                             segM = O_MW1; segS = O_SW1; S0p = SW1; }
        else if (j < 2080) { ofD = OF2_B1D; r = (j-2048)*4; gidx = b*128 + r;
                             segM = O_MB1; segS = O_SB1; S0p = Sb1; }
        else if (j < 4128) { ofD = OF2_W2D; r = (j-2080)*4; gidx = b*8192 + r;
                             segM = O_MW2; segS = O_SW2; S0p = SW2; }
        else               { ofD = OF2_B2D; r = (j-4128)*4; gidx = b*64 + r;
                             segM = O_MB2; segS = O_SB2; S0p = Sb2; }
        const float* pp = g_part + (size_t)(b*NC) * PARTSZ2 + ofD + r;
        float4 rD = make_float4(0.f, 0.f, 0.f, 0.f);
        #pragma unroll
        for (int c = 0; c < NC; c++) {
            float4 v = *(const float4*)(pp + (size_t)c * PARTSZ2);
            rD.x += v.x; rD.y += v.y; rD.z += v.z; rD.w += v.w;
        }
        float4 cr = *(const float4*)(g_corr + (size_t)b * PARTSZ2 + ofD + r);
        const float qT = __expf(-26.262166726f);
        const float aT = qT * 1.0010537407f;
        float4 s0 = *(const float4*)(S0p + gidx);
        float4 M, S;
        M.x = aT*s0.x + rD.x*INV949 + cr.x;  S.x = qT*s0.x + rD.x;
        M.y = aT*s0.y + rD.y*INV949 + cr.y;  S.y = qT*s0.y + rD.y;
        M.z = aT*s0.z + rD.z*INV949 + cr.z;  S.z = qT*s0.z + rD.z;
        M.w = aT*s0.w + rD.w*INV949 + cr.w;  S.w = qT*s0.w + rD.w;
        *(float4*)(out + segM + gidx) = M;
        *(float4*)(out + segS + gidx) = S;
    }

    // ---- loss finalize: last CTA globally computes the 512 loss sums ----
    __syncthreads();
    if (tid == 0) {
        __threadfence();
        unsigned old = atomicAdd(&g_lcount, 1);
        if (old == NCTA - 1) {
            g_lcount = 0;          // self-reset for graph replay
            __threadfence();
            sflag[0] = 1.f;
        } else {
            sflag[0] = 0.f;
        }
    }
    __syncthreads();
    if (sflag[0] != 0.f) {
        for (int gt = tid; gt < 512; gt += THR) {
            float s = 0.f;
            #pragma unroll
            for (int bb = 0; bb < Bz; bb++) s += g_lossp[bb*Tz + gt];
            out[O_LOSS + gt] = s * (1.f/512.f);
        }
    }
}

extern "C" void kernel_launch(void* const* d_in, const int* in_sizes, int n_in,
                              void* d_out, int out_size) {
    const float* x   = (const float*)d_in[0];
    const float* WK  = (const float*)d_in[1];
    const float* WV  = (const float*)d_in[2];
    const float* W1  = (const float*)d_in[3];
    const float* b1  = (const float*)d_in[4];
    const float* W2  = (const float*)d_in[5];
    const float* b2  = (const float*)d_in[6];
    const float* SW1 = (const float*)d_in[7];
    const float* Sb1 = (const float*)d_in[8];
    const float* SW2 = (const float*)d_in[9];
    const float* Sb2 = (const float*)d_in[10];
    float* out = (float*)d_out;

    static const size_t smem_main = SM_FLOATS * sizeof(float);
    cudaFuncSetAttribute(k_main, cudaFuncAttributeMaxDynamicSharedMemorySize,
                         (int)smem_main);

    k_main<<<NCTA, THR, smem_main>>>(x, WK, WV, W1, b1, W2, b2,
                                     SW1, Sb1, SW2, Sb2, out);
}

// round 16
// speedup vs baseline: 1.1389x; 1.1389x over previous
#include <cuda_runtime.h>
#include <math.h>

#define Bz 8
#define Tz 512
#define Ez 64
#define Hz 128
#define TC 32     // tokens per CTA
#define NC 16     // chunks per batch
#define NCTA (Bz*NC)
#define THR 256

#define P1 68
#define P2 132

// Per-CTA partial layout (floats): D-weighted grads only
#define OF2_W1D 0
#define OF2_B1D 8192
#define OF2_W2D 8320
#define OF2_B2D 16512
#define PARTSZ2 16576

// Output offsets
#define O_LOSS 0
#define O_MW1  512
#define O_MB1  66048
#define O_MW2  67072
#define O_MB2  132608
#define O_SW1  133120
#define O_SB1  198656
#define O_SW2  199680
#define O_SB2  265216

#define LNETA  (-0.0512932943875506f)
#define LNBETA (-6.9077552789821370f)
#define INV949 (1.0537407798735f)
#define CORRK  (0.0526870389936f)

__device__ __align__(16) float g_np[2*NCTA*Ez];
__device__ __align__(16) float g_lossp[Bz*Tz];
__device__ __align__(16) float g_part[NCTA*PARTSZ2];
__device__ __align__(16) float g_corr[Bz*PARTSZ2];
__device__ unsigned g_count;
__device__ volatile unsigned g_phase;

__device__ __forceinline__ float fast_sig(float z) {
    return __fdividef(1.f, 1.f + __expf(-z));
}

// ---------------------------------------------------------------------------
// Single fused kernel: 128 CTAs x 256 threads, 255-reg budget (R14 base)
// + distributed norm partial loads overlapped with W1/W2 weight loads.
// ---------------------------------------------------------------------------
#define SM_FLOATS 36512
__global__ __launch_bounds__(THR, 1) void k_main(const float* __restrict__ x,
                                                 const float* __restrict__ WK,
                                                 const float* __restrict__ WV,
                                                 const float* __restrict__ W1,
                                                 const float* __restrict__ b1,
                                                 const float* __restrict__ W2,
                                                 const float* __restrict__ b2,
                                                 const float* __restrict__ SW1,
                                                 const float* __restrict__ Sb1,
                                                 const float* __restrict__ SW2,
                                                 const float* __restrict__ Sb2,
                                                 float* __restrict__ out) {
    extern __shared__ float sm[];
    float* sWK  = sm;                 // 64 x P1
    float* sWV  = sm + 4352;          // 64 x P1
    float* sW1  = sm;                 // 128 x P1 overlay (WK/WV dead)
    float* sx   = sm + 8704;          // 32x64 (phase0 only)
    float* sW2  = sm + 8704;          // 64 x P2 overlay
    float* sk   = sm + 17152;         // 32x64 (raw silu k)
    float* sv   = sk  + 2048;         // 32x64 (raw silu v)
    float* sh   = sv  + 2048;         // 32x128
    float* ss   = sh  + 4096;         // 32x128
    float* sdy  = ss  + 4096;         // 32x64
    float* sdz  = sdy + 2048;         // 32x128
    float* scD  = sdz + 4096;         // 32
    float* scC  = scD + 32;           // 32
    float* sinvk= scC + 32;           // 64
    float* sinvv= sinvk + 64;         // 64
    float* sloss= sinvv + 64;         // 32
    float* sb1  = sloss + 32;         // 128
    float* sb2  = sb1 + 128;          // 64
    float* snk  = sb2 + 64;           // 256 (norm partial staging, k)
    float* snv  = snk + 256;          // 256 (norm partial staging, v) -> 36512

    const int bid = blockIdx.x;
    const int b   = bid >> 4;
    const int t0  = (bid & 15) * TC;
    const int tid = threadIdx.x;
    const int lane = tid & 31, wp = tid >> 5;   // 8 warps, 4 tokens each

    // ---- phase 0 loads ----
    #pragma unroll
    for (int i = tid*4; i < 4096; i += 1024) {
        int e = i >> 6, j = i & 63;
        *(float4*)&sWK[e*P1 + j] = *(const float4*)&WK[i];
        *(float4*)&sWV[e*P1 + j] = *(const float4*)&WV[i];
    }
    #pragma unroll
    for (int i = tid*4; i < 2048; i += 1024)
        *(float4*)&sx[i] = *(const float4*)&x[(b*Tz + t0)*64 + i];
    if (tid < 64)       sinvk[tid] = 0.f;
    else if (tid < 128) sinvv[tid - 64] = 0.f;
    if (tid >= 128 && tid < 160) {
        int tl = tid - 128;
        float n1 = (float)(Tz - (t0 + tl));
        scD[tl] = -0.05f * __expf(n1 * LNETA);
        scC[tl] = CORRK  * __expf(n1 * LNBETA);
    }
    __syncthreads();

    // ---- phase 0: silu projections (4 tokens/warp, 4x4 tiles) ----
    {
        float acc[4][4];
        #pragma unroll
        for (int r = 0; r < 4; r++)
            #pragma unroll
            for (int tt = 0; tt < 4; tt++) acc[r][tt] = 0.f;
        #pragma unroll
        for (int j = 0; j < 64; j += 4) {
            float xv[4][4];
            #pragma unroll
            for (int tt = 0; tt < 4; tt++) {
                float4 q = *(const float4*)&sx[(wp*4 + tt)*64 + j];
                xv[tt][0] = q.x; xv[tt][1] = q.y; xv[tt][2] = q.z; xv[tt][3] = q.w;
            }
            float4 w4[4];
            w4[0] = *(const float4*)&sWK[(lane     )*P1 + j];
            w4[1] = *(const float4*)&sWK[(lane + 32)*P1 + j];
            w4[2] = *(const float4*)&sWV[(lane     )*P1 + j];
            w4[3] = *(const float4*)&sWV[(lane + 32)*P1 + j];
            #pragma unroll
            for (int r = 0; r < 4; r++) {
                const float* w = (const float*)&w4[r];
                #pragma unroll
                for (int jj = 0; jj < 4; jj++)
                    #pragma unroll
                    for (int tt = 0; tt < 4; tt++)
                        acc[r][tt] += w[jj] * xv[tt][jj];
            }
        }
        #pragma unroll
        for (int r = 0; r < 4; r++) {
            int e = lane + 32*(r & 1);
            float sq = 0.f;
            #pragma unroll
            for (int tt = 0; tt < 4; tt++) {
                float z = acc[r][tt];
                float s = z * fast_sig(z);
                int t = wp*4 + tt;
                if (r < 2) sk[t*64 + e] = s;
                else       sv[t*64 + e] = s;
                sq += s * s;
            }
            if (r < 2) atomicAdd(&sinvk[e], sq);
            else       atomicAdd(&sinvv[e], sq);
        }
    }
    __syncthreads();

    if (tid < 64)       g_np[bid*64 + tid] = sinvk[tid];
    else if (tid < 128) g_np[(NCTA + bid)*64 + tid - 64] = sinvv[tid - 64];

    // ---- grid barrier #1 (W1/W2/b1/b2 + norm-partial loads overlap spin) ----
    __threadfence();
    __syncthreads();
    if (tid == 0) {
        unsigned my = g_phase;
        unsigned old = atomicAdd(&g_count, 1);
        if (old == NCTA - 1) {
            g_count = 0;
            __threadfence();
            atomicAdd((unsigned*)&g_phase, 1);
        } else {
            while (g_phase == my) { }
        }
        __threadfence();
    }
    #pragma unroll
    for (int i = tid*4; i < 8192; i += 1024)
        *(float4*)&sW1[(i >> 6)*P1 + (i & 63)] = *(const float4*)&W1[b*8192 + i];
    #pragma unroll
    for (int i = tid*4; i < 8192; i += 1024)
        *(float4*)&sW2[(i >> 7)*P2 + (i & 127)] = *(const float4*)&W2[b*8192 + i];
    if (tid < 128)      sb1[tid] = b1[b*128 + tid];
    else if (tid < 192) sb2[tid - 128] = b2[b*64 + tid - 128];
    // distributed norm partials: tid = (group g)*64 + e ; 4 chunks each
    {
        int e = tid & 63, g = tid >> 6;
        float s = 0.f, s2 = 0.f;
        #pragma unroll
        for (int c = 0; c < 4; c++) {
            s  += g_np[(b*NC + g*4 + c)*64 + e];
            s2 += g_np[(NCTA + b*NC + g*4 + c)*64 + e];
        }
        snk[tid] = s;
        snv[tid] = s2;
    }
    __syncthreads();

    // ---- finish norm reduce (cheap LDS) ----
    if (tid < 64) {
        float s  = snk[tid] + snk[tid+64] + snk[tid+128] + snk[tid+192];
        float s2 = snv[tid] + snv[tid+64] + snv[tid+128] + snv[tid+192];
        sinvk[tid] = (s  > 0.f) ? rsqrtf(s)  : 0.f;
        sinvv[tid] = (s2 > 0.f) ? rsqrtf(s2) : 0.f;
    }
    __syncthreads();

    // ---- z = W1 (k*invk) + b1 ; h = silu(z) ----
    {
        float acc[4][4];
        #pragma unroll
        for (int r = 0; r < 4; r++) {
            float bv = sb1[lane + 32*r];
            #pragma unroll
            for (int tt = 0; tt < 4; tt++) acc[r][tt] = bv;
        }
        #pragma unroll
        for (int j = 0; j < 64; j += 4) {
            float4 iv = *(const float4*)&sinvk[j];
            float kv[4][4];
            #pragma unroll
            for (int tt = 0; tt < 4; tt++) {
                float4 q = *(const float4*)&sk[(wp*4 + tt)*64 + j];
                kv[tt][0] = q.x * iv.x; kv[tt][1] = q.y * iv.y;
                kv[tt][2] = q.z * iv.z; kv[tt][3] = q.w * iv.w;
            }
            float4 w4[4];
            #pragma unroll
            for (int r = 0; r < 4; r++)
                w4[r] = *(const float4*)&sW1[(lane + 32*r)*P1 + j];
            #pragma unroll
            for (int r = 0; r < 4; r++) {
                const float* w = (const float*)&w4[r];
                #pragma unroll
                for (int jj = 0; jj < 4; jj++)
                    #pragma unroll
                    for (int tt = 0; tt < 4; tt++)
                        acc[r][tt] += w[jj] * kv[tt][jj];
            }
        }
        #pragma unroll
        for (int r = 0; r < 4; r++)
            #pragma unroll
            for (int tt = 0; tt < 4; tt++) {
                int idx = (wp*4 + tt)*128 + lane + 32*r;
                float z  = acc[r][tt];
                float sg = fast_sig(z);
                ss[idx] = sg;
                sh[idx] = z * sg;
            }
    }
    __syncwarp();

    // ---- y = W2 h + b2 ; dy = (y - v*invv)/256 ; loss ----
    {
        float acc[2][4];
        #pragma unroll
        for (int r = 0; r < 2; r++) {
            float bv = sb2[lane + 32*r];
            #pragma unroll
            for (int tt = 0; tt < 4; tt++) acc[r][tt] = bv;
        }
        #pragma unroll
        for (int j = 0; j < 128; j += 4) {
            float hv[4][4];
            #pragma unroll
            for (int tt = 0; tt < 4; tt++) {
                float4 q = *(const float4*)&sh[(wp*4 + tt)*128 + j];
                hv[tt][0] = q.x; hv[tt][1] = q.y; hv[tt][2] = q.z; hv[tt][3] = q.w;
            }
            float4 w40 = *(const float4*)&sW2[(lane     )*P2 + j];
            float4 w41 = *(const float4*)&sW2[(lane + 32)*P2 + j];
            const float* w0 = (const float*)&w40;
            const float* w1 = (const float*)&w41;
            #pragma unroll
            for (int jj = 0; jj < 4; jj++)
                #pragma unroll
                for (int tt = 0; tt < 4; tt++) {
                    acc[0][tt] += w0[jj] * hv[tt][jj];
                    acc[1][tt] += w1[jj] * hv[tt][jj];
                }
        }
        float iv0 = sinvv[lane], iv1 = sinvv[lane + 32];
        #pragma unroll
        for (int tt = 0; tt < 4; tt++) {
            int t = wp*4 + tt;
            float d0 = acc[0][tt] - sv[t*64 + lane]      * iv0;
            float d1 = acc[1][tt] - sv[t*64 + lane + 32] * iv1;
            sdy[t*64 + lane]      = d0 * (1.f/256.f);
            sdy[t*64 + lane + 32] = d1 * (1.f/256.f);
            float l = d0*d0 + d1*d1;
            #pragma unroll
            for (int o = 16; o; o >>= 1) l += __shfl_xor_sync(0xffffffffu, l, o);
            if (lane == 0) sloss[t] = l;
        }
    }
    __syncwarp();

    // ---- dh = W2^T dy ; dz ----
    {
        float acc[4][4];
        #pragma unroll
        for (int r = 0; r < 4; r++)
            #pragma unroll
            for (int tt = 0; tt < 4; tt++) acc[r][tt] = 0.f;
        #pragma unroll
        for (int e = 0; e < 64; e += 4) {
            float dv[4][4];
            #pragma unroll
            for (int tt = 0; tt < 4; tt++) {
                float4 q = *(const float4*)&sdy[(wp*4 + tt)*64 + e];
                dv[tt][0] = q.x; dv[tt][1] = q.y; dv[tt][2] = q.z; dv[tt][3] = q.w;
            }
            #pragma unroll
            for (int ee = 0; ee < 4; ee++) {
                float wv[4];
                #pragma unroll
                for (int r = 0; r < 4; r++) wv[r] = sW2[(e + ee)*P2 + lane + 32*r];
                #pragma unroll
                for (int r = 0; r < 4; r++)
                    #pragma unroll
                    for (int tt = 0; tt < 4; tt++)
                        acc[r][tt] += wv[r] * dv[tt][ee];
            }
        }
        #pragma unroll
        for (int r = 0; r < 4; r++)
            #pragma unroll
            for (int tt = 0; tt < 4; tt++) {
                int idx = (wp*4 + tt)*128 + lane + 32*r;
                float sg = ss[idx], hv = sh[idx];
                sdz[idx] = acc[r][tt] * (sg + hv * (1.f - sg));
            }
    }
    __syncthreads();

    // ---- D-weighted outer products: 8h x 4e tile (invk folded into ks) ----
    const int e0 = (tid & 15) * 4;
    const int h0 = (tid >> 4) * 8;
    const float4 ivk = *(const float4*)&sinvk[e0];
    float a1[8][4], a2[4][8];
    #pragma unroll
    for (int i = 0; i < 8; i++)
        #pragma unroll
        for (int j = 0; j < 4; j++) { a1[i][j] = 0.f; a2[j][i] = 0.f; }

    #pragma unroll 4
    for (int t = 0; t < TC; t++) {
        float cd = scD[t];
        float4 kq = *(const float4*)&sk[t*64 + e0];
        float ks[4] = {cd*kq.x*ivk.x, cd*kq.y*ivk.y, cd*kq.z*ivk.z, cd*kq.w*ivk.w};
        float4 z0 = *(const float4*)&sdz[t*128 + h0];
        float4 z1 = *(const float4*)&sdz[t*128 + h0 + 4];
        float dzv[8] = {z0.x, z0.y, z0.z, z0.w, z1.x, z1.y, z1.z, z1.w};
        #pragma unroll
        for (int i = 0; i < 8; i++)
            #pragma unroll
            for (int j = 0; j < 4; j++) a1[i][j] += dzv[i] * ks[j];
        float4 dq = *(const float4*)&sdy[t*64 + e0];
        float dys[4] = {cd*dq.x, cd*dq.y, cd*dq.z, cd*dq.w};
        float4 h0q = *(const float4*)&sh[t*128 + h0];
        float4 h1q = *(const float4*)&sh[t*128 + h0 + 4];
        float hv[8] = {h0q.x, h0q.y, h0q.z, h0q.w, h1q.x, h1q.y, h1q.z, h1q.w};
        #pragma unroll
        for (int j = 0; j < 4; j++)
            #pragma unroll
            for (int i = 0; i < 8; i++) a2[j][i] += dys[j] * hv[i];
    }

    float* p = g_part + (size_t)bid * PARTSZ2;
    #pragma unroll
    for (int i = 0; i < 8; i++)
        *(float4*)&p[OF2_W1D + (h0 + i)*64 + e0] =
            make_float4(a1[i][0], a1[i][1], a1[i][2], a1[i][3]);
    #pragma unroll
    for (int j = 0; j < 4; j++) {
        *(float4*)&p[OF2_W2D + (e0 + j)*128 + h0] =
            make_float4(a2[j][0], a2[j][1], a2[j][2], a2[j][3]);
        *(float4*)&p[OF2_W2D + (e0 + j)*128 + h0 + 4] =
            make_float4(a2[j][4], a2[j][5], a2[j][6], a2[j][7]);
    }
    if (tid < 128) {
        float aD = 0.f;
        #pragma unroll 4
        for (int t = 0; t < TC; t++) aD += scD[t] * sdz[t*128 + tid];
        p[OF2_B1D + tid] = aD;
    } else if (tid < 192) {
        int e = tid - 128;
        float aD = 0.f;
        #pragma unroll 4
        for (int t = 0; t < TC; t++) aD += scD[t] * sdy[t*64 + e];
        p[OF2_B2D + e] = aD;
    }
    if (tid < TC) g_lossp[b*Tz + t0 + tid] = sloss[tid];

    // ---- correction (last chunk per batch; invk folded) ----
    if ((bid & 15) == 15) {
        #pragma unroll
        for (int i = 0; i < 8; i++)
            #pragma unroll
            for (int j = 0; j < 4; j++) { a1[i][j] = 0.f; a2[j][i] = 0.f; }
        for (int t = 16; t < TC; t++) {
            float cc = scC[t];
            float4 kq = *(const float4*)&sk[t*64 + e0];
            float ks[4] = {cc*kq.x*ivk.x, cc*kq.y*ivk.y, cc*kq.z*ivk.z, cc*kq.w*ivk.w};
            float4 z0 = *(const float4*)&sdz[t*128 + h0];
            float4 z1 = *(const float4*)&sdz[t*128 + h0 + 4];
            float dzv[8] = {z0.x, z0.y, z0.z, z0.w, z1.x, z1.y, z1.z, z1.w};
            #pragma unroll
            for (int i = 0; i < 8; i++)
                #pragma unroll
                for (int j = 0; j < 4; j++) a1[i][j] += dzv[i] * ks[j];
            float4 dq = *(const float4*)&sdy[t*64 + e0];
            float dys[4] = {cc*dq.x, cc*dq.y, cc*dq.z, cc*dq.w};
            float4 h0q = *(const float4*)&sh[t*128 + h0];
            float4 h1q = *(const float4*)&sh[t*128 + h0 + 4];
            float hv[8] = {h0q.x, h0q.y, h0q.z, h0q.w, h1q.x, h1q.y, h1q.z, h1q.w};
            #pragma unroll
            for (int j = 0; j < 4; j++)
                #pragma unroll
                for (int i = 0; i < 8; i++) a2[j][i] += dys[j] * hv[i];
        }
        float* q = g_corr + (size_t)b * PARTSZ2;
        #pragma unroll
        for (int i = 0; i < 8; i++)
            *(float4*)&q[OF2_W1D + (h0 + i)*64 + e0] =
                make_float4(a1[i][0], a1[i][1], a1[i][2], a1[i][3]);
        #pragma unroll
        for (int j = 0; j < 4; j++) {
            *(float4*)&q[OF2_W2D + (e0 + j)*128 + h0] =
                make_float4(a2[j][0], a2[j][1], a2[j][2], a2[j][3]);
            *(float4*)&q[OF2_W2D + (e0 + j)*128 + h0 + 4] =
                make_float4(a2[j][4], a2[j][5], a2[j][6], a2[j][7]);
        }
        if (tid < 128) {
            float aC = 0.f;
            for (int t = 16; t < TC; t++) aC += scC[t] * sdz[t*128 + tid];
            q[OF2_B1D + tid] = aC;
        } else if (tid < 192) {
            int e = tid - 128;
            float aC = 0.f;
            for (int t = 16; t < TC; t++) aC += scC[t] * sdy[t*64 + e];
            q[OF2_B2D + e] = aC;
        }
    }

    // ---- grid barrier #2, then fused output reduction (strided) ----
    __threadfence();
    __syncthreads();
    if (tid == 0) {
        unsigned my = g_phase;
        unsigned old = atomicAdd(&g_count, 1);
        if (old == NCTA - 1) {
            g_count = 0;
            __threadfence();
            atomicAdd((unsigned*)&g_phase, 1);
        } else {
            while (g_phase == my) { }
        }
        __threadfence();
    }
    __syncthreads();

    const float qT = __expf(-26.262166726f);    // 0.95^512
    const float aT = qT * 1.0010537407f;        // qT/(1-beta/eta)
    for (int gt = bid * THR + tid; gt < 33664; gt += NCTA * THR) {
        if (gt < 512) {
            float s = 0.f;
            #pragma unroll
            for (int bb = 0; bb < Bz; bb++) s += g_lossp[bb*Tz + gt];
            out[O_LOSS + gt] = s * (1.f/512.f);
            continue;
        }
        int j = gt - 512;
        int ofD, nvec_b, segM, segS;
        const float* S0p;
        if (j < 16384) {
            ofD = OF2_W1D; nvec_b = 2048; segM = O_MW1; segS = O_SW1; S0p = SW1;
        } else if ((j -= 16384) < 256) {
            ofD = OF2_B1D; nvec_b = 32;   segM = O_MB1; segS = O_SB1; S0p = Sb1;
        } else if ((j -= 256) < 16384) {
            ofD = OF2_W2D; nvec_b = 2048; segM = O_MW2; segS = O_SW2; S0p = SW2;
        } else if ((j -= 16384) < 128) {
            ofD = OF2_B2D; nvec_b = 16;   segM = O_MB2; segS = O_SB2; S0p = Sb2;
        } else continue;

        int bb = j / nvec_b;
        int r = (j - bb*nvec_b) * 4;
        const float* pp = g_part + (size_t)(bb*NC) * PARTSZ2 + ofD + r;
        float4 rD = make_float4(0.f, 0.f, 0.f, 0.f);
        #pragma unroll
        for (int c = 0; c < NC; c++) {
            float4 v = *(const float4*)(pp + (size_t)c * PARTSZ2);
            rD.x += v.x; rD.y += v.y; rD.z += v.z; rD.w += v.w;
        }
        float4 cr = *(const float4*)(g_corr + (size_t)bb * PARTSZ2 + ofD + r);
        int gidx = bb * (nvec_b*4) + r;
        float4 s0 = *(const float4*)(S0p + gidx);
        float4 M, S;
        M.x = aT*s0.x + rD.x*INV949 + cr.x;  S.x = qT*s0.x + rD.x;
        M.y = aT*s0.y + rD.y*INV949 + cr.y;  S.y = qT*s0.y + rD.y;
        M.z = aT*s0.z + rD.z*INV949 + cr.z;  S.z = qT*s0.z + rD.z;
        M.w = aT*s0.w + rD.w*INV949 + cr.w;  S.w = qT*s0.w + rD.w;
        *(float4*)(out + segM + gidx) = M;
        *(float4*)(out + segS + gidx) = S;
    }
}

extern "C" void kernel_launch(void* const* d_in, const int* in_sizes, int n_in,
                              void* d_out, int out_size) {
    const float* x   = (const float*)d_in[0];
    const float* WK  = (const float*)d_in[1];
    const float* WV  = (const float*)d_in[2];
    const float* W1  = (const float*)d_in[3];
    const float* b1  = (const float*)d_in[4];
    const float* W2  = (const float*)d_in[5];
    const float* b2  = (const float*)d_in[6];
    const float* SW1 = (const float*)d_in[7];
    const float* Sb1 = (const float*)d_in[8];
    const float* SW2 = (const float*)d_in[9];
    const float* Sb2 = (const float*)d_in[10];
    float* out = (float*)d_out;

    static const size_t smem_main = SM_FLOATS * sizeof(float);
    cudaFuncSetAttribute(k_main, cudaFuncAttributeMaxDynamicSharedMemorySize,
                         (int)smem_main);

    k_main<<<NCTA, THR, smem_main>>>(x, WK, WV, W1, b1, W2, b2,
                                     SW1, Sb1, SW2, Sb2, out);
}